// round 15
// baseline (speedup 1.0000x reference)
#include <cuda_runtime.h>
#include <cuda_fp16.h>

// Problem constants
#define B_   2
#define T_   8
#define BT_  16
#define NQ_  128
#define NK_  128
#define DIN_ 64
#define DOUT_ 256
#define DP_  128     // d-pairs total (DOUT_/2)
#define DPC2_ 32     // d-pairs per staged chunk (4 chunks of 64 d)
#define P16_ 33      // k16 row pitch in half2 words (odd -> conflict-free LDS.32)
#define PT_  68      // kt row pitch in float words (68%32==4 -> conflict-free LDS.128)

// Device-global scratch
__device__ __half2 g_Qh[B_ * NQ_ * DP_];      // raw proj Q, half2 (MUFU path)
__device__ __half2 g_Kh[BT_ * NK_ * DP_];     // raw proj K, half2 (MUFU path)
__device__ float   g_Qt[B_ * NQ_ * DOUT_];    // tanh(proj Q), fp32 (identity path)
__device__ float   g_Kt[BT_ * NK_ * DOUT_];   // tanh(proj K), fp32 (identity path)

__device__ __forceinline__ __half2 h2tanh_mufu(__half2 x) {
    __half2 r;
    asm("tanh.approx.f16x2 %0, %1;"
        : "=r"(*reinterpret_cast<unsigned*>(&r))
        : "r"(*reinterpret_cast<unsigned*>(&x)));
    return r;
}
__device__ __forceinline__ float ftanh(float x) {
    float r;
    asm("tanh.approx.f32 %0, %1;" : "=f"(r) : "f"(x));
    return r;
}

// Exact tanh addition identity, FMA-pipe only (8 FMA-class ops + 1 ALU):
//   tanh(q+k) = (tq+tk) * rcp(1+tq*tk);  den in (0,2) always positive normal.
// rcp: magic seed (ALU int-sub) + 2 Newton -> ~1e-6 rel.
#define IDENT_ACC(tq, tk, vd, acc) do {                                   \
    const float den_ = fmaf((tq), (tk), 1.0f);                            \
    const float num_ = (tq) + (tk);                                       \
    float y_ = __int_as_float(0x7EF311C3 - __float_as_int(den_));         \
    y_ = y_ * fmaf(-den_, y_, 2.0f);                                      \
    y_ = y_ * fmaf(-den_, y_, 2.0f);                                      \
    (acc) = fmaf((vd), num_ * y_, (acc));                                 \
} while (0)

// ---------------------------------------------------------------------------
// Kernel 1: projections (fp32 math), dual-format output (unchanged).
// ---------------------------------------------------------------------------
__global__ void __launch_bounds__(512, 1) proj_kernel(
    const float* __restrict__ query, const float* __restrict__ keys,
    const float* __restrict__ Wq,    const float* __restrict__ Wk,
    const float* __restrict__ bk)
{
    __shared__ float w_sh[32][DOUT_];
    __shared__ float in_sh[16][DIN_];

    const int blk = blockIdx.x;             // 0..143 (16 Q, 128 K)
    const bool isQ = (blk < 16);
    const int r0 = (isQ ? blk : (blk - 16)) * 16;
    const float* __restrict__ in = isQ ? query : keys;
    const float* __restrict__ W  = isQ ? Wq    : Wk;
    __half2* __restrict__ outh   = isQ ? g_Qh  : g_Kh;
    float* __restrict__ outt     = isQ ? g_Qt  : g_Kt;

    const int tid = threadIdx.x;
    const int cg = tid & 63;
    const int rg = tid >> 6;
    const int row0 = rg * 2, row1 = rg * 2 + 1;

    if (tid < 256) {
        const int r = tid >> 4, s = tid & 15;
        *(float4*)&in_sh[r][s * 4] =
            *(const float4*)(in + (size_t)(r0 + r) * DIN_ + s * 4);
    }

    float4 bias = make_float4(0.f, 0.f, 0.f, 0.f);
    if (!isQ) bias = *(const float4*)(bk + cg * 4);
    float4 acc0 = bias, acc1 = bias;

#pragma unroll 1
    for (int kc = 0; kc < 2; kc++) {
        __syncthreads();
#pragma unroll
        for (int j = 0; j < 4; j++) {
            const int f4 = tid + j * 512;
            *(float4*)&w_sh[0][f4 * 4] =
                *(const float4*)(W + (size_t)(kc * 32) * DOUT_ + f4 * 4);
        }
        __syncthreads();

#pragma unroll 4
        for (int i = 0; i < 32; i++) {
            const float4 wv = *(const float4*)&w_sh[i][cg * 4];
            const float x0 = in_sh[row0][kc * 32 + i];
            const float x1 = in_sh[row1][kc * 32 + i];
            acc0.x = fmaf(x0, wv.x, acc0.x);
            acc0.y = fmaf(x0, wv.y, acc0.y);
            acc0.z = fmaf(x0, wv.z, acc0.z);
            acc0.w = fmaf(x0, wv.w, acc0.w);
            acc1.x = fmaf(x1, wv.x, acc1.x);
            acc1.y = fmaf(x1, wv.y, acc1.y);
            acc1.z = fmaf(x1, wv.z, acc1.z);
            acc1.w = fmaf(x1, wv.w, acc1.w);
        }
    }

    {
        __half2 p0 = __floats2half2_rn(acc0.x, acc0.y);
        __half2 p1 = __floats2half2_rn(acc0.z, acc0.w);
        __half2* dst = outh + (size_t)(r0 + row0) * DP_ + cg * 2;
        dst[0] = p0; dst[1] = p1;
    }
    {
        __half2 p0 = __floats2half2_rn(acc1.x, acc1.y);
        __half2 p1 = __floats2half2_rn(acc1.z, acc1.w);
        __half2* dst = outh + (size_t)(r0 + row1) * DP_ + cg * 2;
        dst[0] = p0; dst[1] = p1;
    }
    {
        float4 t = make_float4(ftanh(acc0.x), ftanh(acc0.y),
                               ftanh(acc0.z), ftanh(acc0.w));
        *(float4*)&outt[(size_t)(r0 + row0) * DOUT_ + cg * 4] = t;
    }
    {
        float4 t = make_float4(ftanh(acc1.x), ftanh(acc1.y),
                               ftanh(acc1.z), ftanh(acc1.w));
        *(float4*)&outt[(size_t)(r0 + row1) * DOUT_ + cg * 4] = t;
    }
}

// ---------------------------------------------------------------------------
// Kernel 2: warp-mixed hybrid scores + fused softmax, HIGH OCCUPANCY.
// Grid = 16 bt x 32 qc = 512 blocks x 128 thr (4 warps). Warp w -> q row
// q0+w; lane l -> nk {l, l+32, l+64, l+96}.
// Mix selector (blockIdx ^ w) & 1:
//   0: streams A,B,C = f16x2 MUFU tanh; D = FMA identity (f=0.75)
//   1: streams A,B   = f16x2 MUFU tanh; C,D = FMA identity (f=0.5)
// smem ~32KB -> 6 blocks/SM = 24 warps/SM (6/SMSP, vs R14's 4): covers
// MUFU-16 / identity-chain latency that capped issue at 58.6%.
// ---------------------------------------------------------------------------
__global__ void __launch_bounds__(128, 6) attn_kernel(
    const float* __restrict__ v, float* __restrict__ out)
{
    __shared__ unsigned k16_sh[96 * P16_];  // 12.7 KB: nk 0..95 raw half2
    __shared__ float    kt_sh[64 * PT_];    // 17.4 KB: nk 64..127 tanh'd fp32
    __shared__ unsigned q16_sh[4][DPC2_];   // 0.5 KB
    __shared__ float    qt_sh[4][2 * DPC2_];// 1 KB
    __shared__ unsigned v16_sh[DPC2_];      // 128 B
    __shared__ float    vt_sh[2 * DPC2_];   // 256 B

    const int bt = blockIdx.x >> 5;              // 0..15
    const int q0 = (blockIdx.x & 31) << 2;       // q chunk of 4
    const int b  = bt >> 3;

    const int tid  = threadIdx.x;
    const int w    = tid >> 5;                   // 0..3 = local q row
    const int lane = tid & 31;
    const int fsel = (blockIdx.x ^ w) & 1;       // 0 -> f=0.75, 1 -> f=0.5

    const __half2* __restrict__ khbase = g_Kh + (size_t)(bt * NK_) * DP_;
    const __half2* __restrict__ qhbase = g_Qh + (size_t)(b * NQ_ + q0) * DP_;
    const float*   __restrict__ ktbase = g_Kt + (size_t)(bt * NK_ + 64) * DOUT_;
    const float*   __restrict__ qtbase = g_Qt + (size_t)(b * NQ_ + q0) * DOUT_;

    float acc0 = 0.f, acc1 = 0.f, acc2 = 0.f, acc3 = 0.f;

#pragma unroll 1
    for (int c = 0; c < DP_ / DPC2_; c++) {
        const int d0dp = c * DPC2_;          // dp offset
        const int d0   = c * 2 * DPC2_;      // d offset

        // Stage k16: 96 rows x 8 uint4 (6/thread); scalar STS (odd pitch)
#pragma unroll
        for (int e = tid; e < 96 * 8; e += 128) {
            const int nk = e >> 3, s = e & 7;
            uint4 t = *(const uint4*)(khbase + (size_t)nk * DP_ + d0dp + s * 4);
            unsigned* dst = &k16_sh[nk * P16_ + s * 4];
            dst[0] = t.x; dst[1] = t.y; dst[2] = t.z; dst[3] = t.w;
        }
        // Stage kt: 64 rows (nk 64..127) x 16 float4 (8/thread), pitch 68
#pragma unroll
        for (int e = tid; e < 64 * 16; e += 128) {
            const int nk = e >> 4, s = e & 15;
            float4 t = *(const float4*)(ktbase + (size_t)nk * DOUT_ + d0 + s * 4);
            *(float4*)&kt_sh[nk * PT_ + s * 4] = t;
        }
        // Stage q16: 4 rows x 8 uint4
        if (tid < 32) {
            const int r = tid >> 3, s = tid & 7;
            *(uint4*)&q16_sh[r][s * 4] =
                *(const uint4*)(qhbase + (size_t)r * DP_ + d0dp + s * 4);
        }
        // Stage qt: 4 rows x 16 float4
        if (tid >= 32 && tid < 96) {
            const int e = tid - 32;
            const int r = e >> 4, s = e & 15;
            *(float4*)&qt_sh[r][s * 4] =
                *(const float4*)(qtbase + (size_t)r * DOUT_ + d0 + s * 4);
        }
        // Stage v16 (fp32 -> half2)
        if (tid >= 96) {
            const int i = tid - 96;
            float2 vv = *(const float2*)(v + d0 + 2 * i);
            __half2 hh = __floats2half2_rn(vv.x, vv.y);
            v16_sh[i] = *reinterpret_cast<unsigned*>(&hh);
        }
        // Stage vt (fp32)
        if (tid < 16)
            *(float4*)&vt_sh[tid * 4] = *(const float4*)(v + d0 + tid * 4);
        __syncthreads();

        const unsigned* __restrict__ k0p = &k16_sh[(lane      ) * P16_];
        const unsigned* __restrict__ k1p = &k16_sh[(lane + 32 ) * P16_];
        const unsigned* __restrict__ k2p = &k16_sh[(lane + 64 ) * P16_];
        const float*    __restrict__ kCp = &kt_sh[(lane      ) * PT_];  // nk l+64
        const float*    __restrict__ kDp = &kt_sh[(lane + 32 ) * PT_];  // nk l+96

        if (fsel == 0) {
            // ---- f = 0.75: streams A,B,C MUFU; D identity ----
#pragma unroll 2
            for (int dp8 = 0; dp8 < DPC2_; dp8 += 8) {
                uint4 qa  = *(const uint4*)&q16_sh[w][dp8];
                uint4 qb4 = *(const uint4*)&q16_sh[w][dp8 + 4];
                uint4 va  = *(const uint4*)&v16_sh[dp8];
                uint4 vb4 = *(const uint4*)&v16_sh[dp8 + 4];
                unsigned qr[8] = {qa.x, qa.y, qa.z, qa.w, qb4.x, qb4.y, qb4.z, qb4.w};
                unsigned vr[8] = {va.x, va.y, va.z, va.w, vb4.x, vb4.y, vb4.z, vb4.w};

                __half2 h0 = __float2half2_rn(0.f);
                __half2 h1 = h0, h2 = h0;
#pragma unroll
                for (int j = 0; j < 8; j++) {
                    const int dp = dp8 + j;
                    const __half2 qp = *reinterpret_cast<const __half2*>(&qr[j]);
                    const __half2 vp = *reinterpret_cast<const __half2*>(&vr[j]);
                    __half2 t0 = h2tanh_mufu(__hadd2(qp, *reinterpret_cast<const __half2*>(&k0p[dp])));
                    __half2 t1 = h2tanh_mufu(__hadd2(qp, *reinterpret_cast<const __half2*>(&k1p[dp])));
                    __half2 t2 = h2tanh_mufu(__hadd2(qp, *reinterpret_cast<const __half2*>(&k2p[dp])));
                    h0 = __hfma2(vp, t0, h0);
                    h1 = __hfma2(vp, t1, h1);
                    h2 = __hfma2(vp, t2, h2);
                }
                float2 f0 = __half22float2(h0);
                float2 f1 = __half22float2(h1);
                float2 f2 = __half22float2(h2);
                acc0 += f0.x + f0.y;
                acc1 += f1.x + f1.y;
                acc2 += f2.x + f2.y;

                const int dd = 2 * dp8;
#pragma unroll
                for (int p4 = 0; p4 < 4; p4++) {
                    const float4 kD = *(const float4*)(kDp + dd + p4 * 4);
                    const float4 qD = *(const float4*)&qt_sh[w][dd + p4 * 4];
                    const float4 vD = *(const float4*)&vt_sh[dd + p4 * 4];
                    IDENT_ACC(qD.x, kD.x, vD.x, acc3);
                    IDENT_ACC(qD.y, kD.y, vD.y, acc3);
                    IDENT_ACC(qD.z, kD.z, vD.z, acc3);
                    IDENT_ACC(qD.w, kD.w, vD.w, acc3);
                }
            }
        } else {
            // ---- f = 0.5: streams A,B MUFU; C,D identity ----
#pragma unroll 2
            for (int dp8 = 0; dp8 < DPC2_; dp8 += 8) {
                uint4 qa  = *(const uint4*)&q16_sh[w][dp8];
                uint4 qb4 = *(const uint4*)&q16_sh[w][dp8 + 4];
                uint4 va  = *(const uint4*)&v16_sh[dp8];
                uint4 vb4 = *(const uint4*)&v16_sh[dp8 + 4];
                unsigned qr[8] = {qa.x, qa.y, qa.z, qa.w, qb4.x, qb4.y, qb4.z, qb4.w};
                unsigned vr[8] = {va.x, va.y, va.z, va.w, vb4.x, vb4.y, vb4.z, vb4.w};

                __half2 h0 = __float2half2_rn(0.f);
                __half2 h1 = h0;
#pragma unroll
                for (int j = 0; j < 8; j++) {
                    const int dp = dp8 + j;
                    const __half2 qp = *reinterpret_cast<const __half2*>(&qr[j]);
                    const __half2 vp = *reinterpret_cast<const __half2*>(&vr[j]);
                    __half2 t0 = h2tanh_mufu(__hadd2(qp, *reinterpret_cast<const __half2*>(&k0p[dp])));
                    __half2 t1 = h2tanh_mufu(__hadd2(qp, *reinterpret_cast<const __half2*>(&k1p[dp])));
                    h0 = __hfma2(vp, t0, h0);
                    h1 = __hfma2(vp, t1, h1);
                }
                float2 f0 = __half22float2(h0);
                float2 f1 = __half22float2(h1);
                acc0 += f0.x + f0.y;
                acc1 += f1.x + f1.y;

                const int dd = 2 * dp8;
#pragma unroll
                for (int p4 = 0; p4 < 4; p4++) {
                    const float4 kC = *(const float4*)(kCp + dd + p4 * 4);
                    const float4 kD = *(const float4*)(kDp + dd + p4 * 4);
                    const float4 qD = *(const float4*)&qt_sh[w][dd + p4 * 4];
                    const float4 vD = *(const float4*)&vt_sh[dd + p4 * 4];
                    IDENT_ACC(qD.x, kC.x, vD.x, acc2);
                    IDENT_ACC(qD.y, kC.y, vD.y, acc2);
                    IDENT_ACC(qD.z, kC.z, vD.z, acc2);
                    IDENT_ACC(qD.w, kC.w, vD.w, acc2);
                    IDENT_ACC(qD.x, kD.x, vD.x, acc3);
                    IDENT_ACC(qD.y, kD.y, vD.y, acc3);
                    IDENT_ACC(qD.z, kD.z, vD.z, acc3);
                    IDENT_ACC(qD.w, kD.w, vD.w, acc3);
                }
            }
        }
        __syncthreads();
    }

    // Fused softmax over nk (warp owns the full 128-wide row)
    float m = fmaxf(fmaxf(acc0, acc1), fmaxf(acc2, acc3));
#pragma unroll
    for (int o = 16; o > 0; o >>= 1)
        m = fmaxf(m, __shfl_xor_sync(0xffffffffu, m, o));

    const float e0 = __expf(acc0 - m);
    const float e1 = __expf(acc1 - m);
    const float e2 = __expf(acc2 - m);
    const float e3 = __expf(acc3 - m);
    float ssum = e0 + e1 + e2 + e3;
#pragma unroll
    for (int o = 16; o > 0; o >>= 1)
        ssum += __shfl_xor_sync(0xffffffffu, ssum, o);

    const float rinv = 1.0f / ssum;

    float* __restrict__ orow = out + (size_t)(bt * NQ_ + q0 + w) * NK_;
    orow[lane      ] = e0 * rinv;
    orow[lane + 32 ] = e1 * rinv;
    orow[lane + 64 ] = e2 * rinv;
    orow[lane + 96 ] = e3 * rinv;
}

// ---------------------------------------------------------------------------
extern "C" void kernel_launch(void* const* d_in, const int* in_sizes, int n_in,
                              void* d_out, int out_size)
{
    const float* query = (const float*)d_in[0];
    const float* keys  = (const float*)d_in[1];
    const float* Wq    = (const float*)d_in[2];
    const float* Wk    = (const float*)d_in[3];
    const float* bk    = (const float*)d_in[4];
    const float* v     = (const float*)d_in[5];
    float* out = (float*)d_out;

    proj_kernel<<<144, 512>>>(query, keys, Wq, Wk, bk);
    attn_kernel<<<512, 128>>>(v, out);
}

// round 16
// speedup vs baseline: 1.0051x; 1.0051x over previous
#include <cuda_runtime.h>
#include <cuda_fp16.h>

// Problem constants
#define B_   2
#define T_   8
#define BT_  16
#define NQ_  128
#define NK_  128
#define DIN_ 64
#define DOUT_ 256
#define DP_  128     // d-pairs total
#define DPH2_ 64     // d-pairs per d-half
#define DPC2_ 32     // d-pairs per staged chunk (2 chunks per d-half)
#define P16_ 33      // smem row pitch in half2 words (odd -> conflict-free LDS.32)

// Device-global scratch
__device__ __half2 g_Qh[B_ * NQ_ * DP_];      // raw proj Q, half2 (MUFU path)
__device__ __half2 g_Kh[BT_ * NK_ * DP_];     // raw proj K, half2 (MUFU path)
__device__ float   g_Qt[B_ * NQ_ * DOUT_];    // tanh(proj Q), fp32 (identity path)
__device__ __half2 g_Kth[BT_ * NK_ * DP_];    // tanh(proj K), half2 (identity path)
__device__ float   g_P[2 * BT_ * NQ_ * NK_];  // partial scores per d-half (2 MB)

__device__ __forceinline__ __half2 h2tanh_mufu(__half2 x) {
    __half2 r;
    asm("tanh.approx.f16x2 %0, %1;"
        : "=r"(*reinterpret_cast<unsigned*>(&r))
        : "r"(*reinterpret_cast<unsigned*>(&x)));
    return r;
}
__device__ __forceinline__ float ftanh(float x) {
    float r;
    asm("tanh.approx.f32 %0, %1;" : "=f"(r) : "f"(x));
    return r;
}

// Exact tanh addition identity, FMA-pipe only:
//   tanh(q+k) = (tq+tk) * rcp(1+tq*tk);  den in (0,2) always positive normal.
// rcp: magic seed + 2 Newton -> ~1e-6 rel.
#define IDENT_ACC(tq, tk, vd, acc) do {                                   \
    const float den_ = fmaf((tq), (tk), 1.0f);                            \
    const float num_ = (tq) + (tk);                                       \
    float y_ = __int_as_float(0x7EF311C3 - __float_as_int(den_));         \
    y_ = y_ * fmaf(-den_, y_, 2.0f);                                      \
    y_ = y_ * fmaf(-den_, y_, 2.0f);                                      \
    (acc) = fmaf((vd), num_ * y_, (acc));                                 \
} while (0)

// ---------------------------------------------------------------------------
// Kernel 1: projections (fp32 math), triple-format output:
//   raw half2 (MUFU path, Q+K); tanh fp32 (identity Q); tanh half2 (identity K).
// ---------------------------------------------------------------------------
__global__ void __launch_bounds__(512, 1) proj_kernel(
    const float* __restrict__ query, const float* __restrict__ keys,
    const float* __restrict__ Wq,    const float* __restrict__ Wk,
    const float* __restrict__ bk)
{
    __shared__ float w_sh[32][DOUT_];
    __shared__ float in_sh[16][DIN_];

    const int blk = blockIdx.x;             // 0..143 (16 Q, 128 K)
    const bool isQ = (blk < 16);
    const int r0 = (isQ ? blk : (blk - 16)) * 16;
    const float* __restrict__ in = isQ ? query : keys;
    const float* __restrict__ W  = isQ ? Wq    : Wk;
    __half2* __restrict__ outh   = isQ ? g_Qh  : g_Kh;

    const int tid = threadIdx.x;
    const int cg = tid & 63;
    const int rg = tid >> 6;
    const int row0 = rg * 2, row1 = rg * 2 + 1;

    if (tid < 256) {
        const int r = tid >> 4, s = tid & 15;
        *(float4*)&in_sh[r][s * 4] =
            *(const float4*)(in + (size_t)(r0 + r) * DIN_ + s * 4);
    }

    float4 bias = make_float4(0.f, 0.f, 0.f, 0.f);
    if (!isQ) bias = *(const float4*)(bk + cg * 4);
    float4 acc0 = bias, acc1 = bias;

#pragma unroll 1
    for (int kc = 0; kc < 2; kc++) {
        __syncthreads();
#pragma unroll
        for (int j = 0; j < 4; j++) {
            const int f4 = tid + j * 512;
            *(float4*)&w_sh[0][f4 * 4] =
                *(const float4*)(W + (size_t)(kc * 32) * DOUT_ + f4 * 4);
        }
        __syncthreads();

#pragma unroll 4
        for (int i = 0; i < 32; i++) {
            const float4 wv = *(const float4*)&w_sh[i][cg * 4];
            const float x0 = in_sh[row0][kc * 32 + i];
            const float x1 = in_sh[row1][kc * 32 + i];
            acc0.x = fmaf(x0, wv.x, acc0.x);
            acc0.y = fmaf(x0, wv.y, acc0.y);
            acc0.z = fmaf(x0, wv.z, acc0.z);
            acc0.w = fmaf(x0, wv.w, acc0.w);
            acc1.x = fmaf(x1, wv.x, acc1.x);
            acc1.y = fmaf(x1, wv.y, acc1.y);
            acc1.z = fmaf(x1, wv.z, acc1.z);
            acc1.w = fmaf(x1, wv.w, acc1.w);
        }
    }

    // raw half2 (both Q and K)
    {
        __half2 p0 = __floats2half2_rn(acc0.x, acc0.y);
        __half2 p1 = __floats2half2_rn(acc0.z, acc0.w);
        __half2* dst = outh + (size_t)(r0 + row0) * DP_ + cg * 2;
        dst[0] = p0; dst[1] = p1;
    }
    {
        __half2 p0 = __floats2half2_rn(acc1.x, acc1.y);
        __half2 p1 = __floats2half2_rn(acc1.z, acc1.w);
        __half2* dst = outh + (size_t)(r0 + row1) * DP_ + cg * 2;
        dst[0] = p0; dst[1] = p1;
    }
    // tanh'd
    const float4 t0 = make_float4(ftanh(acc0.x), ftanh(acc0.y),
                                  ftanh(acc0.z), ftanh(acc0.w));
    const float4 t1 = make_float4(ftanh(acc1.x), ftanh(acc1.y),
                                  ftanh(acc1.z), ftanh(acc1.w));
    if (isQ) {
        *(float4*)&g_Qt[(size_t)(r0 + row0) * DOUT_ + cg * 4] = t0;
        *(float4*)&g_Qt[(size_t)(r0 + row1) * DOUT_ + cg * 4] = t1;
    } else {
        __half2* d0 = g_Kth + (size_t)(r0 + row0) * DP_ + cg * 2;
        d0[0] = __floats2half2_rn(t0.x, t0.y);
        d0[1] = __floats2half2_rn(t0.z, t0.w);
        __half2* d1 = g_Kth + (size_t)(r0 + row1) * DP_ + cg * 2;
        d1[0] = __floats2half2_rn(t1.x, t1.y);
        d1[1] = __floats2half2_rn(t1.z, t1.w);
    }
}

// ---------------------------------------------------------------------------
// Kernel 2: warp-mixed hybrid partial scores over a d-half.
// Grid = 16 bt x 16 qc x 2 dh = 512 blocks x 256 thr (8 warps). Warp w ->
// q row qc*8+w; lane l -> nk {l, l+32, l+64, l+96}.
// Mix selector (blockIdx ^ w) & 1:
//   0: A,B,C = f16x2 MUFU tanh; D = FMA identity (f=0.75)
//   1: A,B   = f16x2 MUFU tanh; C,D = FMA identity (f=0.5)
// smem 24.6KB + launch_bounds(256,3) (85 regs) + 512 blocks
//   -> 3 blocks/SM = 24 warps/SM (6/SMSP): covers MUFU/identity latency
//   that pinned issue at 56-59% at 16 warps/SM.
// ---------------------------------------------------------------------------
__global__ void __launch_bounds__(256, 3) attn_partial_kernel(
    const float* __restrict__ v)
{
    __shared__ unsigned k16_sh[96 * P16_];   // 12.7 KB: nk 0..95 raw half2
    __shared__ unsigned kt16_sh[64 * P16_];  // 8.4 KB : nk 64..127 tanh'd half2
    __shared__ unsigned q16_sh[8][DPC2_];    // 1 KB
    __shared__ float    qt_sh[8][2 * DPC2_]; // 2 KB
    __shared__ unsigned v16_sh[DPC2_];       // 128 B
    __shared__ float    vt_sh[2 * DPC2_];    // 256 B

    const int blk = blockIdx.x;
    const int dh  = blk & 1;                     // d-half
    const int qc  = (blk >> 1) & 15;             // q chunk of 8
    const int bt  = blk >> 5;                    // 0..15
    const int b   = bt >> 3;

    const int tid  = threadIdx.x;
    const int w    = tid >> 5;
    const int lane = tid & 31;
    const int fsel = (blk ^ w) & 1;              // 0 -> f=0.75, 1 -> f=0.5

    const __half2* __restrict__ khbase = g_Kh  + (size_t)(bt * NK_) * DP_;
    const __half2* __restrict__ qhbase = g_Qh  + (size_t)(b * NQ_ + qc * 8) * DP_;
    const __half2* __restrict__ ktbase = g_Kth + (size_t)(bt * NK_ + 64) * DP_;
    const float*   __restrict__ qtbase = g_Qt  + (size_t)(b * NQ_ + qc * 8) * DOUT_;

    float acc0 = 0.f, acc1 = 0.f, acc2 = 0.f, acc3 = 0.f;

#pragma unroll 1
    for (int c = 0; c < 2; c++) {
        const int d0dp = dh * DPH2_ + c * DPC2_;   // dp offset
        const int d0   = 2 * d0dp;                 // d offset

        // Stage k16: 96 rows x 8 uint4 (3/thread); scalar STS (odd pitch)
#pragma unroll
        for (int e = tid; e < 96 * 8; e += 256) {
            const int nk = e >> 3, s = e & 7;
            uint4 t = *(const uint4*)(khbase + (size_t)nk * DP_ + d0dp + s * 4);
            unsigned* dst = &k16_sh[nk * P16_ + s * 4];
            dst[0] = t.x; dst[1] = t.y; dst[2] = t.z; dst[3] = t.w;
        }
        // Stage kt16: 64 rows (nk 64..127) x 8 uint4 (2/thread)
#pragma unroll
        for (int e = tid; e < 64 * 8; e += 256) {
            const int nk = e >> 3, s = e & 7;
            uint4 t = *(const uint4*)(ktbase + (size_t)nk * DP_ + d0dp + s * 4);
            unsigned* dst = &kt16_sh[nk * P16_ + s * 4];
            dst[0] = t.x; dst[1] = t.y; dst[2] = t.z; dst[3] = t.w;
        }
        // Stage q16: 8 rows x 8 uint4
        if (tid < 64) {
            const int r = tid >> 3, s = tid & 7;
            *(uint4*)&q16_sh[r][s * 4] =
                *(const uint4*)(qhbase + (size_t)r * DP_ + d0dp + s * 4);
        }
        // Stage qt: 8 rows x 16 float4
        if (tid >= 64 && tid < 192) {
            const int e = tid - 64;
            const int r = e >> 4, s = e & 15;
            *(float4*)&qt_sh[r][s * 4] =
                *(const float4*)(qtbase + (size_t)r * DOUT_ + d0 + s * 4);
        }
        // Stage v16 (fp32 -> half2)
        if (tid >= 192 && tid < 224) {
            const int i = tid - 192;
            float2 vv = *(const float2*)(v + d0 + 2 * i);
            __half2 hh = __floats2half2_rn(vv.x, vv.y);
            v16_sh[i] = *reinterpret_cast<unsigned*>(&hh);
        }
        // Stage vt (fp32)
        if (tid >= 224 && tid < 240) {
            const int s = tid - 224;
            *(float4*)&vt_sh[s * 4] = *(const float4*)(v + d0 + s * 4);
        }
        __syncthreads();

        const unsigned* __restrict__ k0p = &k16_sh[(lane      ) * P16_];
        const unsigned* __restrict__ k1p = &k16_sh[(lane + 32 ) * P16_];
        const unsigned* __restrict__ k2p = &k16_sh[(lane + 64 ) * P16_];
        const unsigned* __restrict__ kCp = &kt16_sh[(lane      ) * P16_]; // nk l+64
        const unsigned* __restrict__ kDp = &kt16_sh[(lane + 32 ) * P16_]; // nk l+96

        if (fsel == 0) {
            // ---- f = 0.75: streams A,B,C MUFU; D identity ----
#pragma unroll 2
            for (int dp8 = 0; dp8 < DPC2_; dp8 += 8) {
                uint4 qa  = *(const uint4*)&q16_sh[w][dp8];
                uint4 qb4 = *(const uint4*)&q16_sh[w][dp8 + 4];
                uint4 va  = *(const uint4*)&v16_sh[dp8];
                uint4 vb4 = *(const uint4*)&v16_sh[dp8 + 4];
                unsigned qr[8] = {qa.x, qa.y, qa.z, qa.w, qb4.x, qb4.y, qb4.z, qb4.w};
                unsigned vr[8] = {va.x, va.y, va.z, va.w, vb4.x, vb4.y, vb4.z, vb4.w};

                __half2 h0 = __float2half2_rn(0.f);
                __half2 h1 = h0, h2 = h0;
#pragma unroll
                for (int j = 0; j < 8; j++) {
                    const int dp = dp8 + j;
                    const __half2 qp = *reinterpret_cast<const __half2*>(&qr[j]);
                    const __half2 vp = *reinterpret_cast<const __half2*>(&vr[j]);
                    __half2 t0 = h2tanh_mufu(__hadd2(qp, *reinterpret_cast<const __half2*>(&k0p[dp])));
                    __half2 t1 = h2tanh_mufu(__hadd2(qp, *reinterpret_cast<const __half2*>(&k1p[dp])));
                    __half2 t2 = h2tanh_mufu(__hadd2(qp, *reinterpret_cast<const __half2*>(&k2p[dp])));
                    h0 = __hfma2(vp, t0, h0);
                    h1 = __hfma2(vp, t1, h1);
                    h2 = __hfma2(vp, t2, h2);

                    // identity stream D, 2 d per dp
                    const unsigned kraw = kDp[dp];
                    const float2 kf = __half22float2(*reinterpret_cast<const __half2*>(&kraw));
                    const float2 qf = *(const float2*)&qt_sh[w][2 * dp];
                    const float2 vf = *(const float2*)&vt_sh[2 * dp];
                    IDENT_ACC(qf.x, kf.x, vf.x, acc3);
                    IDENT_ACC(qf.y, kf.y, vf.y, acc3);
                }
                float2 f0 = __half22float2(h0);
                float2 f1 = __half22float2(h1);
                float2 f2 = __half22float2(h2);
                acc0 += f0.x + f0.y;
                acc1 += f1.x + f1.y;
                acc2 += f2.x + f2.y;
            }
        } else {
            // ---- f = 0.5: streams A,B MUFU; C,D identity ----
#pragma unroll 2
            for (int dp8 = 0; dp8 < DPC2_; dp8 += 8) {
                uint4 qa  = *(const uint4*)&q16_sh[w][dp8];
                uint4 qb4 = *(const uint4*)&q16_sh[w][dp8 + 4];
                uint4 va  = *(const uint4*)&v16_sh[dp8];
                uint4 vb4 = *(const uint4*)&v16_sh[dp8 + 4];
                unsigned qr[8] = {qa.x, qa.y, qa.z, qa.w, qb4.x, qb4.y, qb4.z, qb4.w};
                unsigned vr[8] = {va.x, va.y, va.z, va.w, vb4.x, vb4.y, vb4.z, vb4.w};

                __half2 h0 = __float2half2_rn(0.f);
                __half2 h1 = h0;
#pragma unroll
                for (int j = 0; j < 8; j++) {
                    const int dp = dp8 + j;
                    const __half2 qp = *reinterpret_cast<const __half2*>(&qr[j]);
                    const __half2 vp = *reinterpret_cast<const __half2*>(&vr[j]);
                    __half2 t0 = h2tanh_mufu(__hadd2(qp, *reinterpret_cast<const __half2*>(&k0p[dp])));
                    __half2 t1 = h2tanh_mufu(__hadd2(qp, *reinterpret_cast<const __half2*>(&k1p[dp])));
                    h0 = __hfma2(vp, t0, h0);
                    h1 = __hfma2(vp, t1, h1);

                    // identity streams C, D
                    const unsigned kcr = kCp[dp];
                    const unsigned kdr = kDp[dp];
                    const float2 kc2 = __half22float2(*reinterpret_cast<const __half2*>(&kcr));
                    const float2 kd2 = __half22float2(*reinterpret_cast<const __half2*>(&kdr));
                    const float2 qf = *(const float2*)&qt_sh[w][2 * dp];
                    const float2 vf = *(const float2*)&vt_sh[2 * dp];
                    IDENT_ACC(qf.x, kc2.x, vf.x, acc2);
                    IDENT_ACC(qf.y, kc2.y, vf.y, acc2);
                    IDENT_ACC(qf.x, kd2.x, vf.x, acc3);
                    IDENT_ACC(qf.y, kd2.y, vf.y, acc3);
                }
                float2 f0 = __half22float2(h0);
                float2 f1 = __half22float2(h1);
                acc0 += f0.x + f0.y;
                acc1 += f1.x + f1.y;
            }
        }
        __syncthreads();
    }

    // Write partials: g_P[dh][bt][q][nk], coalesced 32-lane groups
    float* __restrict__ prow =
        g_P + ((size_t)dh * BT_ * NQ_ + (size_t)(bt * NQ_ + qc * 8 + w)) * NK_;
    prow[lane      ] = acc0;
    prow[lane + 32 ] = acc1;
    prow[lane + 64 ] = acc2;
    prow[lane + 96 ] = acc3;
}

// ---------------------------------------------------------------------------
// Kernel 3: combine d-halves + softmax (R6-proven).
// ---------------------------------------------------------------------------
__global__ void __launch_bounds__(256) combine_kernel(float* __restrict__ out)
{
    const int tid  = threadIdx.x;
    const int w    = tid >> 5;
    const int lane = tid & 31;
    const int r    = blockIdx.x * 8 + w;

    const float* __restrict__ p0 = g_P + (size_t)r * NK_;
    const float* __restrict__ p1 = g_P + (size_t)(BT_ * NQ_ + r) * NK_;

    float4 a = *(const float4*)(p0 + lane * 4);
    float4 c = *(const float4*)(p1 + lane * 4);
    float4 s = make_float4(a.x + c.x, a.y + c.y, a.z + c.z, a.w + c.w);

    float m = fmaxf(fmaxf(s.x, s.y), fmaxf(s.z, s.w));
#pragma unroll
    for (int o = 16; o > 0; o >>= 1)
        m = fmaxf(m, __shfl_xor_sync(0xffffffffu, m, o));

    float4 e = make_float4(__expf(s.x - m), __expf(s.y - m),
                           __expf(s.z - m), __expf(s.w - m));
    float ssum = e.x + e.y + e.z + e.w;
#pragma unroll
    for (int o = 16; o > 0; o >>= 1)
        ssum += __shfl_xor_sync(0xffffffffu, ssum, o);

    const float rinv = 1.0f / ssum;
    float4 res = make_float4(e.x * rinv, e.y * rinv, e.z * rinv, e.w * rinv);
    *(float4*)(out + (size_t)r * NK_ + lane * 4) = res;
}

// ---------------------------------------------------------------------------
extern "C" void kernel_launch(void* const* d_in, const int* in_sizes, int n_in,
                              void* d_out, int out_size)
{
    const float* query = (const float*)d_in[0];
    const float* keys  = (const float*)d_in[1];
    const float* Wq    = (const float*)d_in[2];
    const float* Wk    = (const float*)d_in[3];
    const float* bk    = (const float*)d_in[4];
    const float* v     = (const float*)d_in[5];
    float* out = (float*)d_out;

    proj_kernel<<<144, 512>>>(query, keys, Wq, Wk, bk);
    attn_partial_kernel<<<512, 256>>>(v);
    combine_kernel<<<256, 256>>>(out);
}

// round 17
// speedup vs baseline: 1.0609x; 1.0554x over previous
#include <cuda_runtime.h>
#include <cuda_fp16.h>

// Problem constants
#define B_   2
#define T_   8
#define BT_  16
#define NQ_  128
#define NK_  128
#define DIN_ 64
#define DOUT_ 256
#define DP_  128     // d-pairs total
#define DPH2_ 64     // d-pairs per d-half
#define DPC2_ 32     // d-pairs per staged chunk (2 chunks per d-half)
#define P16_ 33      // smem row pitch in half2 words (odd -> conflict-free LDS.32)

// Device-global scratch
__device__ __half2 g_Qh[B_ * NQ_ * DP_];      // raw proj Q, half2 (MUFU path)
__device__ __half2 g_Kh[BT_ * NK_ * DP_];     // raw proj K, half2 (MUFU path)
__device__ float   g_Qt[B_ * NQ_ * DOUT_];    // tanh(proj Q), fp32 (identity path)
__device__ __half2 g_Kth[BT_ * NK_ * DP_];    // tanh(proj K), half2 (identity path)
__device__ float   g_P[2 * BT_ * NQ_ * NK_];  // partial scores per d-half (2 MB)

__device__ __forceinline__ __half2 h2tanh_mufu(__half2 x) {
    __half2 r;
    asm("tanh.approx.f16x2 %0, %1;"
        : "=r"(*reinterpret_cast<unsigned*>(&r))
        : "r"(*reinterpret_cast<unsigned*>(&x)));
    return r;
}
__device__ __forceinline__ float ftanh(float x) {
    float r;
    asm("tanh.approx.f32 %0, %1;" : "=f"(r) : "f"(x));
    return r;
}

// Exact tanh addition identity, FMA-pipe only:
//   tanh(q+k) = (tq+tk) * rcp(1+tq*tk);  den in (0,2) always positive normal.
// rcp: magic seed + 2 Newton -> ~1e-6 rel.
#define IDENT_ACC(tq, tk, vd, acc) do {                                   \
    const float den_ = fmaf((tq), (tk), 1.0f);                            \
    const float num_ = (tq) + (tk);                                       \
    float y_ = __int_as_float(0x7EF311C3 - __float_as_int(den_));         \
    y_ = y_ * fmaf(-den_, y_, 2.0f);                                      \
    y_ = y_ * fmaf(-den_, y_, 2.0f);                                      \
    (acc) = fmaf((vd), num_ * y_, (acc));                                 \
} while (0)

// ---------------------------------------------------------------------------
// Kernel 1: projections (fp32 math), triple-format output.
// 288 blocks (8 rows each) x 256 thr, 2 blocks/SM, W register
// double-buffered (best measured proj: 7.2us cold).
// ---------------------------------------------------------------------------
__global__ void __launch_bounds__(256, 2) proj_kernel(
    const float* __restrict__ query, const float* __restrict__ keys,
    const float* __restrict__ Wq,    const float* __restrict__ Wk,
    const float* __restrict__ bk)
{
    __shared__ float in_sh[8][DIN_];

    const int blk = blockIdx.x;            // 0..287 (32 Q blocks, 256 K blocks)
    const bool isQ = (blk < 32);
    const int r0 = (isQ ? blk : (blk - 32)) * 8;
    const float* __restrict__ in = isQ ? query : keys;
    const float* __restrict__ W  = isQ ? Wq    : Wk;
    __half2* __restrict__ outh   = isQ ? g_Qh  : g_Kh;

    const int tid = threadIdx.x;
    const int cg = tid & 63;                // cols 4*cg..4*cg+3
    const int rg = tid >> 6;                // rows rg*2, rg*2+1

    if (tid < 128) {
        const int r = tid >> 4, s = tid & 15;
        *(float4*)&in_sh[r][s * 4] =
            *(const float4*)(in + (size_t)(r0 + r) * DIN_ + s * 4);
    }
    __syncthreads();

    float4 bias = make_float4(0.f, 0.f, 0.f, 0.f);
    if (!isQ) bias = *(const float4*)(bk + cg * 4);

    float4 acc0 = bias, acc1 = bias;
    const int row0 = rg * 2, row1 = rg * 2 + 1;

    float4 wcur[8], wnxt[8];
#pragma unroll
    for (int i = 0; i < 8; i++)
        wcur[i] = *(const float4*)(W + (size_t)i * DOUT_ + cg * 4);

#pragma unroll
    for (int ic = 0; ic < 8; ic++) {
        if (ic < 7) {
#pragma unroll
            for (int i = 0; i < 8; i++)
                wnxt[i] = *(const float4*)(W + (size_t)((ic + 1) * 8 + i) * DOUT_ + cg * 4);
        }
#pragma unroll
        for (int i = 0; i < 8; i++) {
            const float x0 = in_sh[row0][ic * 8 + i];
            const float x1 = in_sh[row1][ic * 8 + i];
            acc0.x = fmaf(x0, wcur[i].x, acc0.x);
            acc0.y = fmaf(x0, wcur[i].y, acc0.y);
            acc0.z = fmaf(x0, wcur[i].z, acc0.z);
            acc0.w = fmaf(x0, wcur[i].w, acc0.w);
            acc1.x = fmaf(x1, wcur[i].x, acc1.x);
            acc1.y = fmaf(x1, wcur[i].y, acc1.y);
            acc1.z = fmaf(x1, wcur[i].z, acc1.z);
            acc1.w = fmaf(x1, wcur[i].w, acc1.w);
        }
#pragma unroll
        for (int i = 0; i < 8; i++) wcur[i] = wnxt[i];
    }

    // raw half2 (both Q and K)
    {
        __half2* dst = outh + (size_t)(r0 + row0) * DP_ + cg * 2;
        dst[0] = __floats2half2_rn(acc0.x, acc0.y);
        dst[1] = __floats2half2_rn(acc0.z, acc0.w);
    }
    {
        __half2* dst = outh + (size_t)(r0 + row1) * DP_ + cg * 2;
        dst[0] = __floats2half2_rn(acc1.x, acc1.y);
        dst[1] = __floats2half2_rn(acc1.z, acc1.w);
    }
    // tanh'd outputs
    const float4 t0 = make_float4(ftanh(acc0.x), ftanh(acc0.y),
                                  ftanh(acc0.z), ftanh(acc0.w));
    const float4 t1 = make_float4(ftanh(acc1.x), ftanh(acc1.y),
                                  ftanh(acc1.z), ftanh(acc1.w));
    if (isQ) {
        *(float4*)&g_Qt[(size_t)(r0 + row0) * DOUT_ + cg * 4] = t0;
        *(float4*)&g_Qt[(size_t)(r0 + row1) * DOUT_ + cg * 4] = t1;
    } else {
        __half2* d0 = g_Kth + (size_t)(r0 + row0) * DP_ + cg * 2;
        d0[0] = __floats2half2_rn(t0.x, t0.y);
        d0[1] = __floats2half2_rn(t0.z, t0.w);
        __half2* d1 = g_Kth + (size_t)(r0 + row1) * DP_ + cg * 2;
        d1[0] = __floats2half2_rn(t1.x, t1.y);
        d1[1] = __floats2half2_rn(t1.z, t1.w);
    }
}

// ---------------------------------------------------------------------------
// Kernel 2: warp-mixed hybrid partial scores over a d-half.
// Grid = 16 bt x 16 qc x 2 dh = 512 blocks x 256 thr. smem = 24.0 KB and
// launch_bounds(256,4) (64 regs) -> 4 blocks/SM, 512 <= 592 capacity ->
// ONE wave (R16 lesson: 3/SM capacity made 1.15 waves -> 15% tail).
// 32 warps/SM = 8/SMSP: covers MUFU-16 / identity-chain latency.
// Mix (blk^w)&1: 0 -> A,B,C MUFU + D identity (f=0.75); 1 -> A,B MUFU +
// C,D identity (f=0.5); SMSP average f=0.625 = LP optimum.
// ---------------------------------------------------------------------------
__global__ void __launch_bounds__(256, 4) attn_partial_kernel(
    const float* __restrict__ v)
{
    __shared__ unsigned k16_sh[96 * P16_];   // 12672 B: nk 0..95 raw half2
    __shared__ unsigned kt16_sh[64 * P16_];  //  8448 B: nk 64..127 tanh'd half2
    __shared__ unsigned q16_sh[8][DPC2_];    //  1024 B
    __shared__ float    qt_sh[8][2 * DPC2_]; //  2048 B
    __shared__ unsigned v16_sh[DPC2_];       //   128 B
    __shared__ float    vt_sh[2 * DPC2_];    //   256 B   -> 24576 B total

    const int blk = blockIdx.x;
    const int dh  = blk & 1;                     // d-half
    const int qc  = (blk >> 1) & 15;             // q chunk of 8
    const int bt  = blk >> 5;                    // 0..15
    const int b   = bt >> 3;

    const int tid  = threadIdx.x;
    const int w    = tid >> 5;
    const int lane = tid & 31;
    const int fsel = (blk ^ w) & 1;              // 0 -> f=0.75, 1 -> f=0.5

    const __half2* __restrict__ khbase = g_Kh  + (size_t)(bt * NK_) * DP_;
    const __half2* __restrict__ qhbase = g_Qh  + (size_t)(b * NQ_ + qc * 8) * DP_;
    const __half2* __restrict__ ktbase = g_Kth + (size_t)(bt * NK_ + 64) * DP_;
    const float*   __restrict__ qtbase = g_Qt  + (size_t)(b * NQ_ + qc * 8) * DOUT_;

    float acc0 = 0.f, acc1 = 0.f, acc2 = 0.f, acc3 = 0.f;

#pragma unroll 1
    for (int c = 0; c < 2; c++) {
        const int d0dp = dh * DPH2_ + c * DPC2_;   // dp offset
        const int d0   = 2 * d0dp;                 // d offset

        // Stage k16: 96 rows x 8 uint4 (3/thread); scalar STS (odd pitch)
#pragma unroll
        for (int e = tid; e < 96 * 8; e += 256) {
            const int nk = e >> 3, s = e & 7;
            uint4 t = *(const uint4*)(khbase + (size_t)nk * DP_ + d0dp + s * 4);
            unsigned* dst = &k16_sh[nk * P16_ + s * 4];
            dst[0] = t.x; dst[1] = t.y; dst[2] = t.z; dst[3] = t.w;
        }
        // Stage kt16: 64 rows (nk 64..127) x 8 uint4 (2/thread)
#pragma unroll
        for (int e = tid; e < 64 * 8; e += 256) {
            const int nk = e >> 3, s = e & 7;
            uint4 t = *(const uint4*)(ktbase + (size_t)nk * DP_ + d0dp + s * 4);
            unsigned* dst = &kt16_sh[nk * P16_ + s * 4];
            dst[0] = t.x; dst[1] = t.y; dst[2] = t.z; dst[3] = t.w;
        }
        // Stage q16: 8 rows x 8 uint4
        if (tid < 64) {
            const int r = tid >> 3, s = tid & 7;
            *(uint4*)&q16_sh[r][s * 4] =
                *(const uint4*)(qhbase + (size_t)r * DP_ + d0dp + s * 4);
        }
        // Stage qt: 8 rows x 16 float4
        if (tid >= 64 && tid < 192) {
            const int e = tid - 64;
            const int r = e >> 4, s = e & 15;
            *(float4*)&qt_sh[r][s * 4] =
                *(const float4*)(qtbase + (size_t)r * DOUT_ + d0 + s * 4);
        }
        // Stage v16 (fp32 -> half2)
        if (tid >= 192 && tid < 224) {
            const int i = tid - 192;
            float2 vv = *(const float2*)(v + d0 + 2 * i);
            __half2 hh = __floats2half2_rn(vv.x, vv.y);
            v16_sh[i] = *reinterpret_cast<unsigned*>(&hh);
        }
        // Stage vt (fp32)
        if (tid >= 224 && tid < 240) {
            const int s = tid - 224;
            *(float4*)&vt_sh[s * 4] = *(const float4*)(v + d0 + s * 4);
        }
        __syncthreads();

        const unsigned* __restrict__ k0p = &k16_sh[(lane      ) * P16_];
        const unsigned* __restrict__ k1p = &k16_sh[(lane + 32 ) * P16_];
        const unsigned* __restrict__ k2p = &k16_sh[(lane + 64 ) * P16_];
        const unsigned* __restrict__ kCp = &kt16_sh[(lane      ) * P16_]; // nk l+64
        const unsigned* __restrict__ kDp = &kt16_sh[(lane + 32 ) * P16_]; // nk l+96

        if (fsel == 0) {
            // ---- f = 0.75: streams A,B,C MUFU; D identity ----
#pragma unroll 2
            for (int dp8 = 0; dp8 < DPC2_; dp8 += 8) {
                __half2 h0 = __float2half2_rn(0.f);
                __half2 h1 = h0, h2 = h0;
#pragma unroll
                for (int j = 0; j < 8; j++) {
                    const int dp = dp8 + j;
                    const unsigned qraw = q16_sh[w][dp];
                    const unsigned vraw = v16_sh[dp];
                    const __half2 qp = *reinterpret_cast<const __half2*>(&qraw);
                    const __half2 vp = *reinterpret_cast<const __half2*>(&vraw);
                    __half2 t0 = h2tanh_mufu(__hadd2(qp, *reinterpret_cast<const __half2*>(&k0p[dp])));
                    __half2 t1 = h2tanh_mufu(__hadd2(qp, *reinterpret_cast<const __half2*>(&k1p[dp])));
                    __half2 t2 = h2tanh_mufu(__hadd2(qp, *reinterpret_cast<const __half2*>(&k2p[dp])));
                    h0 = __hfma2(vp, t0, h0);
                    h1 = __hfma2(vp, t1, h1);
                    h2 = __hfma2(vp, t2, h2);

                    // identity stream D, 2 d per dp
                    const unsigned kraw = kDp[dp];
                    const float2 kf = __half22float2(*reinterpret_cast<const __half2*>(&kraw));
                    const float2 qf = *(const float2*)&qt_sh[w][2 * dp];
                    const float2 vf = *(const float2*)&vt_sh[2 * dp];
                    IDENT_ACC(qf.x, kf.x, vf.x, acc3);
                    IDENT_ACC(qf.y, kf.y, vf.y, acc3);
                }
                float2 f0 = __half22float2(h0);
                float2 f1 = __half22float2(h1);
                float2 f2 = __half22float2(h2);
                acc0 += f0.x + f0.y;
                acc1 += f1.x + f1.y;
                acc2 += f2.x + f2.y;
            }
        } else {
            // ---- f = 0.5: streams A,B MUFU; C,D identity ----
#pragma unroll 2
            for (int dp8 = 0; dp8 < DPC2_; dp8 += 8) {
                __half2 h0 = __float2half2_rn(0.f);
                __half2 h1 = h0;
#pragma unroll
                for (int j = 0; j < 8; j++) {
                    const int dp = dp8 + j;
                    const unsigned qraw = q16_sh[w][dp];
                    const unsigned vraw = v16_sh[dp];
                    const __half2 qp = *reinterpret_cast<const __half2*>(&qraw);
                    const __half2 vp = *reinterpret_cast<const __half2*>(&vraw);
                    __half2 t0 = h2tanh_mufu(__hadd2(qp, *reinterpret_cast<const __half2*>(&k0p[dp])));
                    __half2 t1 = h2tanh_mufu(__hadd2(qp, *reinterpret_cast<const __half2*>(&k1p[dp])));
                    h0 = __hfma2(vp, t0, h0);
                    h1 = __hfma2(vp, t1, h1);

                    // identity streams C, D
                    const unsigned kcr = kCp[dp];
                    const unsigned kdr = kDp[dp];
                    const float2 kc2 = __half22float2(*reinterpret_cast<const __half2*>(&kcr));
                    const float2 kd2 = __half22float2(*reinterpret_cast<const __half2*>(&kdr));
                    const float2 qf = *(const float2*)&qt_sh[w][2 * dp];
                    const float2 vf = *(const float2*)&vt_sh[2 * dp];
                    IDENT_ACC(qf.x, kc2.x, vf.x, acc2);
                    IDENT_ACC(qf.y, kc2.y, vf.y, acc2);
                    IDENT_ACC(qf.x, kd2.x, vf.x, acc3);
                    IDENT_ACC(qf.y, kd2.y, vf.y, acc3);
                }
                float2 f0 = __half22float2(h0);
                float2 f1 = __half22float2(h1);
                acc0 += f0.x + f0.y;
                acc1 += f1.x + f1.y;
            }
        }
        __syncthreads();
    }

    // Write partials: g_P[dh][bt][q][nk], coalesced 32-lane groups
    float* __restrict__ prow =
        g_P + ((size_t)dh * BT_ * NQ_ + (size_t)(bt * NQ_ + qc * 8 + w)) * NK_;
    prow[lane      ] = acc0;
    prow[lane + 32 ] = acc1;
    prow[lane + 64 ] = acc2;
    prow[lane + 96 ] = acc3;
}

// ---------------------------------------------------------------------------
// Kernel 3: combine d-halves + softmax.
// ---------------------------------------------------------------------------
__global__ void __launch_bounds__(256) combine_kernel(float* __restrict__ out)
{
    const int tid  = threadIdx.x;
    const int w    = tid >> 5;
    const int lane = tid & 31;
    const int r    = blockIdx.x * 8 + w;

    const float* __restrict__ p0 = g_P + (size_t)r * NK_;
    const float* __restrict__ p1 = g_P + (size_t)(BT_ * NQ_ + r) * NK_;

    float4 a = *(const float4*)(p0 + lane * 4);
    float4 c = *(const float4*)(p1 + lane * 4);
    float4 s = make_float4(a.x + c.x, a.y + c.y, a.z + c.z, a.w + c.w);

    float m = fmaxf(fmaxf(s.x, s.y), fmaxf(s.z, s.w));
#pragma unroll
    for (int o = 16; o > 0; o >>= 1)
        m = fmaxf(m, __shfl_xor_sync(0xffffffffu, m, o));

    float4 e = make_float4(__expf(s.x - m), __expf(s.y - m),
                           __expf(s.z - m), __expf(s.w - m));
    float ssum = e.x + e.y + e.z + e.w;
#pragma unroll
    for (int o = 16; o > 0; o >>= 1)
        ssum += __shfl_xor_sync(0xffffffffu, ssum, o);

    const float rinv = 1.0f / ssum;
    float4 res = make_float4(e.x * rinv, e.y * rinv, e.z * rinv, e.w * rinv);
    *(float4*)(out + (size_t)r * NK_ + lane * 4) = res;
}

// ---------------------------------------------------------------------------
extern "C" void kernel_launch(void* const* d_in, const int* in_sizes, int n_in,
                              void* d_out, int out_size)
{
    const float* query = (const float*)d_in[0];
    const float* keys  = (const float*)d_in[1];
    const float* Wq    = (const float*)d_in[2];
    const float* Wk    = (const float*)d_in[3];
    const float* bk    = (const float*)d_in[4];
    const float* v     = (const float*)d_in[5];
    float* out = (float*)d_out;

    proj_kernel<<<288, 256>>>(query, keys, Wq, Wk, bk);
    attn_partial_kernel<<<512, 256>>>(v);
    combine_kernel<<<256, 256>>>(out);
}